// round 9
// baseline (speedup 1.0000x reference)
#include <cuda_runtime.h>
#include <cuda_fp16.h>
#include <cstdint>

// ---------------- problem constants ----------------
#define HH 80
#define WW 120
#define TT 12
#define FF 32
#define NPX (HH*WW)

#define TILY 20
#define TILX 8
#define NTILES 60        // (80/20) * (120/8)
#define NTHREADS 640     // 20 warps: warp 0-9 -> batch 0 strip, 10-19 -> batch 1

#define HROWS 22
#define HCOLS 10
#define NHALO 220        // halo pixels per batch
#define PXB 112          // pixel stride bytes in smem (56 f16; 48 used)

// channel order per pixel: [state 0..31 | x 32..37 | zeros 38..47]
#define KW 440           // f16 per weight row (432 = 9*48, + 8 pad)
#define WRB 880          // weight row stride bytes

#define SM_HALO_B (2*NHALO*PXB)   // 49280 (both batches)
#define SM_WA_B   (64*WRB)        // 56320
#define SM_WB_B   (32*WRB)        // 28160

// ---------------- global scratch (no allocation allowed) ----------------
__device__ __half g_wAh[2*64*KW];        // [dir][n][k] gate weights
__device__ __half g_wBh[2*32*KW];        // [dir][n][k] candidate weights
__device__ float  g_h  [2*2*NPX*FF];     // fp32 state (exact bypass path)
__device__ float  g_z  [2*2*NPX*FF];     // fp32 update gate
__device__ __half g_hf [2*2*NPX*FF];     // f16 state mirror (conv operand)
__device__ __half g_rhf[2*2*NPX*FF];     // f16 r*h (conv operand)
__device__ __half g_xf8[2*TT*NPX*8];     // x preconverted: 8 f16/px (6 + 2 zeros)

// ---------------- helpers ----------------
__device__ __forceinline__ uint32_t smem_u32(const void* p) {
    uint32_t a;
    asm("{ .reg .u64 t; cvta.to.shared.u64 t, %1; cvt.u32.u64 %0, t; }" : "=r"(a) : "l"(p));
    return a;
}
__device__ __forceinline__ float sigm(float v) {
    return __fdividef(1.0f, 1.0f + __expf(-v));
}
__device__ __forceinline__ float ftanh(float v) {
    float e = __expf(-2.0f * v);
    return __fdividef(1.0f - e, 1.0f + e);
}
__device__ __forceinline__ void ldm_x4(uint32_t& r0, uint32_t& r1, uint32_t& r2, uint32_t& r3,
                                       uint32_t addr) {
    asm volatile("ldmatrix.sync.aligned.m8n8.x4.shared.b16 {%0,%1,%2,%3}, [%4];"
                 : "=r"(r0), "=r"(r1), "=r"(r2), "=r"(r3) : "r"(addr));
}
__device__ __forceinline__ void mma16816(float* c,
                                         uint32_t a0, uint32_t a1, uint32_t a2, uint32_t a3,
                                         uint32_t b0, uint32_t b1) {
    asm volatile("mma.sync.aligned.m16n8k16.row.col.f32.f16.f16.f32 "
                 "{%0,%1,%2,%3}, {%4,%5,%6,%7}, {%8,%9}, {%0,%1,%2,%3};"
                 : "+f"(c[0]), "+f"(c[1]), "+f"(c[2]), "+f"(c[3])
                 : "r"(a0), "r"(a1), "r"(a2), "r"(a3), "r"(b0), "r"(b1));
}

// ---------------- one-time packs ----------------
// weights: row n, k = tap*48 + c; c<32 = state ch, 32..37 = x ch, else 0
__global__ void pack_kernel(const float* __restrict__ WxF, const float* __restrict__ WzrF,
                            const float* __restrict__ WhF,
                            const float* __restrict__ WxB, const float* __restrict__ WzrB,
                            const float* __restrict__ WhB)
{
    const int TOT = 2*96*KW;
    for (int i = blockIdx.x*blockDim.x + threadIdx.x; i < TOT; i += gridDim.x*blockDim.x) {
        int dir = i / (96*KW); int r = i - dir*(96*KW);
        int n96 = r / KW;      int k = r - n96*KW;
        float v = 0.0f;
        if (k < 432) {
            int tap = k / 48, c = k - tap*48;
            const float* Wx  = dir ? WxB  : WxF;
            const float* Wzr = dir ? WzrB : WzrF;
            const float* Wh  = dir ? WhB  : WhF;
            if (c < 32) {
                if (n96 < 64) v = Wzr[(tap*32 + c)*64 + n96];
                else          v = Wh [(tap*32 + c)*32 + (n96 - 64)];
            } else if (c < 38) {
                v = Wx[(tap*6 + (c - 32))*96 + n96];
            }
        }
        __half hv = __float2half_rn(v);
        if (n96 < 64) g_wAh[(dir*64 + n96)*KW + k]        = hv;
        else          g_wBh[(dir*32 + (n96 - 64))*KW + k] = hv;
    }
}

__global__ void convert_x_kernel(const float* __restrict__ x) {
    const int n = 2*TT*NPX;
    for (int p = blockIdx.x*blockDim.x + threadIdx.x; p < n; p += gridDim.x*blockDim.x) {
        const float* src = x + (size_t)p*6;
        __half2 h0 = __floats2half2_rn(src[0], src[1]);
        __half2 h1 = __floats2half2_rn(src[2], src[3]);
        __half2 h2 = __floats2half2_rn(src[4], src[5]);
        uint4 v;
        v.x = *(uint32_t*)&h0; v.y = *(uint32_t*)&h1; v.z = *(uint32_t*)&h2; v.w = 0u;
        *(uint4*)(g_xf8 + (size_t)p*8) = v;
    }
}

__global__ void zero_h_kernel() {
    const int n = 2*2*NPX*FF;
    for (int i = blockIdx.x*blockDim.x + threadIdx.x; i < n; i += gridDim.x*blockDim.x) {
        g_h[i] = 0.0f;
        if (i < n/2) ((uint32_t*)g_hf)[i] = 0u;
    }
}

// ---------------- halo staging: pure aligned f16 copies ----------------
__device__ __forceinline__ void stage_halo(char* sHalo, const __half* __restrict__ stf,
                                           int dir, int t, int ty0, int tx0, int tid)
{
    if (tid < 2*NHALO) {
        const int hb  = tid / NHALO;          // batch
        const int hpx = tid - hb*NHALO;
        const int sy = hpx / HCOLS, sx = hpx - sy*HCOLS;
        const int gy = ty0 + sy - 1, gx = tx0 + sx - 1;
        uint4* dst = (uint4*)(sHalo + tid*PXB);
        if (gy >= 0 && gy < HH && gx >= 0 && gx < WW) {
            const uint4* hs = (const uint4*)(stf + (size_t)((dir*2 + hb)*NPX + gy*WW + gx)*FF);
            dst[0] = hs[0]; dst[1] = hs[1]; dst[2] = hs[2]; dst[3] = hs[3];
            dst[4] = *(const uint4*)(g_xf8 + (size_t)((hb*TT + t)*NPX + gy*WW + gx)*8);
            dst[5] = make_uint4(0u,0u,0u,0u);
            dst[6] = make_uint4(0u,0u,0u,0u);
        } else {
            uint4 z = make_uint4(0u,0u,0u,0u);
            #pragma unroll
            for (int j = 0; j < 7; ++j) dst[j] = z;
        }
    }
}

// ---------------- Kernel A: gates -> z (fp32), r*h (f16 mirror) ----------------
__global__ void __launch_bounds__(NTHREADS)
stepA(const float* __restrict__ bF, const float* __restrict__ bB, int s)
{
    extern __shared__ char smc[];
    char* sHalo = smc;
    char* sW    = smc + SM_HALO_B;

    const int dir = blockIdx.y, tile = blockIdx.x;
    const int ty0 = (tile / 15) * TILY, tx0 = (tile % 15) * TILX;
    const int t   = dir ? (TT - 1 - s) : s;
    const int tid = threadIdx.x;
    const float* bias = dir ? bB : bF;

    {   // weights -> smem
        const uint4* src = (const uint4*)(g_wAh + (size_t)dir*64*KW);
        uint4* dst = (uint4*)sW;
        for (int i = tid; i < SM_WA_B/16; i += NTHREADS) dst[i] = src[i];
    }
    stage_halo(sHalo, g_hf, dir, t, ty0, tx0, tid);
    __syncthreads();

    const int warp = tid >> 5, lane = tid & 31;
    const int wb = warp / 10, wl = warp - wb*10;       // batch, warp-in-batch
    const uint32_t haloB = smem_u32(sHalo) + (uint32_t)(wb*NHALO*PXB);
    const uint32_t wB0   = smem_u32(sW);

    const int py  = 2*wl + ((lane & 15) >> 3);
    const int pxl = lane & 7;
    const uint32_t aHalf = (uint32_t)((lane >> 4) << 4);
    const uint32_t bThr = wB0 + (((uint32_t)((lane >> 4) << 3) + (uint32_t)(lane & 7))*WRB)
                              + (uint32_t)(((lane >> 3) & 1) << 4);

    float C[8][4];
    #pragma unroll
    for (int j = 0; j < 8; ++j) { C[j][0]=C[j][1]=C[j][2]=C[j][3]=0.0f; }

    #pragma unroll
    for (int ky = 0; ky < 3; ++ky)
    #pragma unroll
    for (int kx = 0; kx < 3; ++kx) {
        const int tap = ky*3 + kx;
        const uint32_t aAddr = haloB + (uint32_t)(((py + ky)*HCOLS + pxl + kx)*PXB) + aHalf;
        const uint32_t bTap  = bThr + (uint32_t)(tap*96);
        #pragma unroll
        for (int ch = 0; ch < 3; ++ch) {
            uint32_t a0,a1,a2,a3;
            ldm_x4(a0,a1,a2,a3, aAddr + ch*32);
            #pragma unroll
            for (int jp = 0; jp < 4; ++jp) {
                uint32_t b0,b1,b2,b3;
                ldm_x4(b0,b1,b2,b3, bTap + (uint32_t)(jp*16*WRB) + ch*32);
                mma16816(C[2*jp],     a0,a1,a2,a3, b0,b1);
                mma16816(C[2*jp + 1], a0,a1,a2,a3, b2,b3);
            }
        }
    }

    // epilogue
    const int gy0 = ty0 + 2*wl;
    const int gx  = tx0 + (lane >> 2);
    const int fc  = (lane & 3) * 2;
    const size_t sob = (size_t)(dir*2 + wb)*NPX*FF;
    #pragma unroll
    for (int j = 0; j < 8; ++j) {
        const int f = j*8 + fc;               // 0..63 (z:0-31, r:32-63)
        const float b0v = bias[f], b1v = bias[f+1];
        #pragma unroll
        for (int rr = 0; rr < 2; ++rr) {
            const int gy = gy0 + rr;
            const size_t pb = sob + (size_t)(gy*WW + gx)*FF;
            const float v0 = C[j][2*rr]   + b0v;
            const float v1 = C[j][2*rr+1] + b1v;
            if (j < 4) {
                *(float2*)(g_z + pb + f) = make_float2(sigm(v0), sigm(v1));
            } else {
                float2 hv = *(const float2*)(g_h + pb + (f - 32));
                *(__half2*)(g_rhf + pb + (f - 32)) =
                    __floats2half2_rn(sigm(v0)*hv.x, sigm(v1)*hv.y);
            }
        }
    }
}

// ---------------- Kernel B: candidate + GRU update ----------------
__global__ void __launch_bounds__(NTHREADS)
stepB(const float* __restrict__ bF, const float* __restrict__ bB,
      float* __restrict__ out, int s)
{
    extern __shared__ char smc[];
    char* sHalo = smc;
    char* sW    = smc + SM_HALO_B;

    const int dir = blockIdx.y, tile = blockIdx.x;
    const int ty0 = (tile / 15) * TILY, tx0 = (tile % 15) * TILX;
    const int t   = dir ? (TT - 1 - s) : s;
    const int tid = threadIdx.x;
    const float* bias = dir ? bB : bF;

    {
        const uint4* src = (const uint4*)(g_wBh + (size_t)dir*32*KW);
        uint4* dst = (uint4*)sW;
        for (int i = tid; i < SM_WB_B/16; i += NTHREADS) dst[i] = src[i];
    }
    stage_halo(sHalo, g_rhf, dir, t, ty0, tx0, tid);
    __syncthreads();

    const int warp = tid >> 5, lane = tid & 31;
    const int wb = warp / 10, wl = warp - wb*10;
    const uint32_t haloB = smem_u32(sHalo) + (uint32_t)(wb*NHALO*PXB);
    const uint32_t wB0   = smem_u32(sW);

    const int py  = 2*wl + ((lane & 15) >> 3);
    const int pxl = lane & 7;
    const uint32_t aHalf = (uint32_t)((lane >> 4) << 4);
    const uint32_t bThr = wB0 + (((uint32_t)((lane >> 4) << 3) + (uint32_t)(lane & 7))*WRB)
                              + (uint32_t)(((lane >> 3) & 1) << 4);

    float C[4][4];
    #pragma unroll
    for (int j = 0; j < 4; ++j) { C[j][0]=C[j][1]=C[j][2]=C[j][3]=0.0f; }

    #pragma unroll
    for (int ky = 0; ky < 3; ++ky)
    #pragma unroll
    for (int kx = 0; kx < 3; ++kx) {
        const int tap = ky*3 + kx;
        const uint32_t aAddr = haloB + (uint32_t)(((py + ky)*HCOLS + pxl + kx)*PXB) + aHalf;
        const uint32_t bTap  = bThr + (uint32_t)(tap*96);
        #pragma unroll
        for (int ch = 0; ch < 3; ++ch) {
            uint32_t a0,a1,a2,a3;
            ldm_x4(a0,a1,a2,a3, aAddr + ch*32);
            #pragma unroll
            for (int jp = 0; jp < 2; ++jp) {
                uint32_t b0,b1,b2,b3;
                ldm_x4(b0,b1,b2,b3, bTap + (uint32_t)(jp*16*WRB) + ch*32);
                mma16816(C[2*jp],     a0,a1,a2,a3, b0,b1);
                mma16816(C[2*jp + 1], a0,a1,a2,a3, b2,b3);
            }
        }
    }

    const int gy0 = ty0 + 2*wl;
    const int gx  = tx0 + (lane >> 2);
    const int fc  = (lane & 3) * 2;
    const size_t sob = (size_t)(dir*2 + wb)*NPX*FF;
    const int b = wb;
    #pragma unroll
    for (int j = 0; j < 4; ++j) {
        const int f = j*8 + fc;               // 0..31
        const float b0v = bias[64 + f], b1v = bias[64 + f + 1];
        #pragma unroll
        for (int rr = 0; rr < 2; ++rr) {
            const int gy = gy0 + rr;
            const size_t pb = sob + (size_t)(gy*WW + gx)*FF;
            float2 z = *(const float2*)(g_z + pb + f);
            float2 h = *(const float2*)(g_h + pb + f);
            const float hh0 = ftanh(C[j][2*rr]   + b0v);
            const float hh1 = ftanh(C[j][2*rr+1] + b1v);
            float2 hn = make_float2(z.x*h.x + (1.0f - z.x)*hh0,
                                    z.y*h.y + (1.0f - z.y)*hh1);
            *(float2*)(g_h + pb + f)  = hn;
            *(__half2*)(g_hf + pb + f) = __floats2half2_rn(hn.x, hn.y);
            *(float2*)(out + ((size_t)((b*TT + t)*HH + gy)*WW + gx)*64 + dir*32 + f) = hn;
        }
    }
}

extern "C" void kernel_launch(void* const* d_in, const int* in_sizes, int n_in,
                              void* d_out, int out_size)
{
    const float* x    = (const float*)d_in[0];
    const float* WxF  = (const float*)d_in[1];
    const float* bF   = (const float*)d_in[2];
    const float* WzrF = (const float*)d_in[3];
    const float* WhF  = (const float*)d_in[4];
    const float* WxB  = (const float*)d_in[5];
    const float* bB   = (const float*)d_in[6];
    const float* WzrB = (const float*)d_in[7];
    const float* WhB  = (const float*)d_in[8];
    float* out = (float*)d_out;

    const int smA = SM_HALO_B + SM_WA_B;   // 105600 B
    const int smB = SM_HALO_B + SM_WB_B;   // 77440 B
    cudaFuncSetAttribute(stepA, cudaFuncAttributeMaxDynamicSharedMemorySize, smA);
    cudaFuncSetAttribute(stepB, cudaFuncAttributeMaxDynamicSharedMemorySize, smB);

    pack_kernel<<<96, 256>>>(WxF, WzrF, WhF, WxB, WzrB, WhB);
    convert_x_kernel<<<256, 256>>>(x);
    zero_h_kernel<<<256, 256>>>();

    dim3 grid(NTILES, 2);   // 60 tiles x 2 dir = 120 blocks (single wave)
    for (int s = 0; s < TT; ++s) {
        stepA<<<grid, NTHREADS, smA>>>(bF, bB, s);
        stepB<<<grid, NTHREADS, smB>>>(bF, bB, out, s);
    }
}